// round 9
// baseline (speedup 1.0000x reference)
#include <cuda_runtime.h>
#include <cuda_fp16.h>
#include <cstdint>
#include <cstddef>

// Problem constants
#define TT 20
#define BB 1024
#define DD 2312
#define D4 578            // DD / 4, exact

// Persistent kernel: 147 blocks x 896 threads, 1 block/SM (~74.5KB smem).
// Blocks 0..145 own 7 rows each; block 146 owns rows 1022..1023.
#define NBLK 147
#define NTHR 896
#define GSZ  128          // threads per row-group
#define NGRP 7            // max rows per block
#define NS4  5            // ceil(578/128) float4 slots per thread
#define TAIL4 66          // 578 - 4*128

#define L2E 1.4426950408889634f

// Grid barrier + per-timestep binding-strength accumulators. Restored to
// initial values every launch (20 sense flips -> back to 0; count reset by the
// last arriver; bsum slots cleaned one barrier late) -> graph replays are
// deterministic.
__device__ unsigned g_count = 0;
__device__ unsigned g_sense = 0;
__device__ float    g_bsum[TT];

__device__ __forceinline__ float warp_sum(float v) {
#pragma unroll
    for (int o = 16; o > 0; o >>= 1)
        v += __shfl_xor_sync(0xffffffffu, v, o);
    return v;
}

__device__ __forceinline__ float ex2a(float x) {
    float y; asm("ex2.approx.ftz.f32 %0, %1;" : "=f"(y) : "f"(x)); return y;
}
__device__ __forceinline__ float rcpa(float x) {
    float y; asm("rcp.approx.ftz.f32 %0, %1;" : "=f"(y) : "f"(x)); return y;
}
__device__ __forceinline__ float tanha(float x) {
    float y; asm("tanh.approx.f32 %0, %1;" : "=f"(y) : "f"(x)); return y;
}
// exact-path sigmoid (2 MUFU) — spike output, error lands directly on out
__device__ __forceinline__ float sigm(float x) {
    return rcpa(1.0f + ex2a(-x * L2E));
}
// cheap sigmoid via tanh (1 MUFU) — compression mask, error attenuated >>1e3x
__device__ __forceinline__ float sigm_t(float x) {
    return fmaf(0.5f, tanha(0.5f * x), 0.5f);
}

__device__ __forceinline__ void pref_l2(const void* p) {
    asm volatile("prefetch.global.L2 [%0];" :: "l"(p));
}

__device__ __forceinline__ unsigned want_of(int k) { return (unsigned)((k + 1) & 1); }

__global__ void __launch_bounds__(NTHR, 1)
snn_etad_kernel(const float* __restrict__ x,
                const float* __restrict__ ac,
                const float* __restrict__ tw,
                const float* __restrict__ ig,
                const float* __restrict__ p_md,
                const float* __restrict__ p_sd,
                const float* __restrict__ p_th,
                float* __restrict__ out)
{
    extern __shared__ char smraw[];
    // c ping-pong: [2][NGRP][D4*2] half2 (fp16 compressed values)
    __half2* s_c  = (__half2*)smraw;                    // 2*7*1156 half2
    __half2* s_ag = s_c + 2 * NGRP * D4 * 2;            // DD half2 {a, g}
    float*   s_rS = (float*)(s_ag + DD);                // 32
    float*   s_rW = s_rS + 32;                          // 32
    float*   s_rA = s_rW + 32;                          // 2 x 32 ping-pong
    float*   s_bsv = s_rA + 64;                         // 1
    volatile int* s_step = (volatile int*)(s_bsv + 1);  // 1

    const int tid  = threadIdx.x;
    const int grp  = tid >> 7;         // 0..6 row-group
    const int gtid = tid & 127;
    const int w    = tid >> 5;         // 0..27
    const int lane = tid & 31;

    int nrows = BB - NGRP * (int)blockIdx.x;
    nrows = nrows > NGRP ? NGRP : nrows;          // 7 or 2 (block 146)
    const bool rowact = grp < nrows;
    const int b = NGRP * blockIdx.x + grp;        // valid when rowact

    const float md = p_md[0];
    const float sd = p_sd[0];
    const float th = p_th[0];
    const float inv_bd = 1.0f / (float)(BB * DD);

    // Init per-feature gates (fp16 packed {a, g})
    for (int idx = tid; idx < DD; idx += NTHR) {
        const float a = ac[idx];
        const float g = sigm(tw[idx]) * sigm(ig[idx]);
        s_ag[idx] = __floats2half2_rn(a, g);
    }
    if (tid == 0) *s_step = 0;
    __syncthreads();

    // LIF state in registers (thread-private across all steps)
    float4 ir[NS4], vr[NS4];
#pragma unroll
    for (int s = 0; s < NS4; ++s) {
        ir[s] = make_float4(0.f, 0.f, 0.f, 0.f);
        vr[s] = make_float4(0.f, 0.f, 0.f, 0.f);
    }

    // L2 prefetch of x(t) for this thread's slots
    auto pref_x = [&](int t) {
        if (!rowact || t >= TT) return;
        const float4* xrow4 = (const float4*)(x + ((size_t)t * BB + b) * DD);
#pragma unroll
        for (int s = 0; s < NS4; ++s) {
            const int d4 = s * GSZ + gtid;
            const bool act = (s < NS4 - 1) || (gtid < TAIL4);
            if (act) pref_l2(xrow4 + d4);
        }
    };

    // ============ pass1+pass2 for timestep t: writes c(t) fp16 into ping-pong
    // slot (t&1), returns this warp's |c| sum (0 for inactive groups).
    auto compute_c = [&](int t) -> float {
        if (!rowact) return 0.0f;
        const float4* xrow4 = (const float4*)(x + ((size_t)t * BB + b) * DD);
        float4 xv[NS4];
        float S = 0.0f, W = 0.0f;
#pragma unroll
        for (int s = 0; s < NS4; ++s) {
            const int d4 = s * GSZ + gtid;
            const bool act = (s < NS4 - 1) || (gtid < TAIL4);
            if (act) {
                const float4 v = __ldg(xrow4 + d4);
                xv[s] = v;
                float e;
                e = ex2a(v.x * L2E); S += e; W += v.x * e;
                e = ex2a(v.y * L2E); S += e; W += v.y * e;
                e = ex2a(v.z * L2E); S += e; W += v.z * e;
                e = ex2a(v.w * L2E); S += e; W += v.w * e;
            }
        }
        S = warp_sum(S);
        W = warp_sum(W);
        if (lane == 0) { s_rS[w] = S; s_rW[w] = W; }
        asm volatile("bar.sync %0, %1;" :: "r"(grp + 1), "n"(GSZ) : "memory");
        S = s_rS[grp * 4 + 0] + s_rS[grp * 4 + 1] + s_rS[grp * 4 + 2] + s_rS[grp * 4 + 3];
        W = s_rW[grp * 4 + 0] + s_rW[grp * 4 + 1] + s_rW[grp * 4 + 2] + s_rW[grp * 4 + 3];
        // entropy = lnS - W/S - D*1e-8  (shift-invariant; |x|<~6 so no overflow)
        const float ent = __logf(S) - __fdividef(W, S) - (float)DD * 1e-8f;

        __half2* sc2 = s_c + ((unsigned)t & 1) * (NGRP * D4 * 2) + grp * (D4 * 2);
        float asum = 0.0f;
#pragma unroll
        for (int s = 0; s < NS4; ++s) {
            const int d4 = s * GSZ + gtid;
            const bool act = (s < NS4 - 1) || (gtid < TAIL4);
            if (act) {
                const uint4 agp = *(const uint4*)(s_ag + 4 * d4);
                const float2 ag0 = __half22float2(((const __half2*)&agp)[0]);
                const float2 ag1 = __half22float2(((const __half2*)&agp)[1]);
                const float2 ag2 = __half22float2(((const __half2*)&agp)[2]);
                const float2 ag3 = __half22float2(((const __half2*)&agp)[3]);
                float4 c = xv[s];
                c.x = c.x * sigm_t(ag0.x * ent) * ag0.y;
                c.y = c.y * sigm_t(ag1.x * ent) * ag1.y;
                c.z = c.z * sigm_t(ag2.x * ent) * ag2.y;
                c.w = c.w * sigm_t(ag3.x * ent) * ag3.y;
                sc2[d4 * 2 + 0] = __floats2half2_rn(c.x, c.y);
                sc2[d4 * 2 + 1] = __floats2half2_rn(c.z, c.w);
                asum += fabsf(c.x) + fabsf(c.y) + fabsf(c.z) + fabsf(c.w);
            }
        }
        return warp_sum(asum);
    };

    // ============ block-level |c| sum -> s_rA ping-pong + sync + warp0 reduce
    auto post_asum = [&](int k, float asum) -> float {
        if (lane == 0) s_rA[((unsigned)k & 1) * 32 + w] = asum;
        __syncthreads();
        float tot = 0.0f;
        if (w == 0) {
            const float vv = (lane < (NTHR / 32)) ? s_rA[((unsigned)k & 1) * 32 + lane] : 0.0f;
            tot = warp_sum(vv);
        }
        return tot;  // valid in warp 0 only
    };

    // ============ tid0: arrive at global barrier k with this block's total
    auto arrive = [&](int k, float tot) {
        atomicAdd(&g_bsum[k], tot);
        __threadfence();
        const unsigned pos = atomicAdd(&g_count, 1);
        if (pos == NBLK - 1) {
            atomicExch(&g_count, 0u);
            atomicExch(&g_bsum[(k + TT - 1) % TT], 0.0f);   // clean stale slot
            __threadfence();
            atomicExch(&g_sense, want_of(k));
        }
    };

    // ---------------- prologue: c(0) -> slot 0, arrive(0); prefetch x(1)
    {
        pref_x(1);
        float asum = compute_c(0);
        float tot = post_asum(0, asum);
        if (tid == 0) arrive(0, tot);
    }

    for (int t = 0; t < TT; ++t) {
        // ---- pass1+2 for t+1 (independent of bs(t)) hides barrier latency
        float tot = 0.0f;
        const bool has_next = (t + 1) < TT;
        if (has_next) {
            float asum = compute_c(t + 1);
            tot = post_asum(t + 1, asum);
        } else {
            __syncthreads();
        }

        // ---- prefetch x(t+2) DRAM->L2; lands during poll + pass3(t)
        pref_x(t + 2);

        // ---- tid0: wait barrier t (released ~1 compute-iteration ago),
        //      publish bs(t), then arrive barrier t+1
        if (tid == 0) {
            const unsigned want = want_of(t);
            while (*((volatile unsigned*)&g_sense) != want) __nanosleep(32);
            __threadfence();
            const float bsv = atomicAdd(&g_bsum[t], 0.0f);   // coherent read
            *(volatile float*)s_bsv = bsv * inv_bd;
            __threadfence_block();
            *s_step = t + 1;                                  // publish
            if (has_next) arrive(t + 1, tot);
        }

        // ---- per-warp pickup (warps stagger straight into pass3)
        float bs;
        if (lane == 0) {
            while (*s_step < t + 1) { }
            bs = *(volatile float*)s_bsv;
        }
        bs = __shfl_sync(0xffffffffu, bs, 0);

        // ---- pass3: LIF on c(t) (fp16 ping-pong slot t&1), state in regs
        if (rowact) {
            const __half2* sc2 = s_c + ((unsigned)t & 1) * (NGRP * D4 * 2) + grp * (D4 * 2);
            float4* o4 = (float4*)(out + ((size_t)t * BB + b) * DD);
#pragma unroll
            for (int s = 0; s < NS4; ++s) {
                const int d4 = s * GSZ + gtid;
                const bool act = (s < NS4 - 1) || (gtid < TAIL4);
                if (act) {
                    const float2 c01 = __half22float2(sc2[d4 * 2 + 0]);
                    const float2 c23 = __half22float2(sc2[d4 * 2 + 1]);
                    float4 sp;

                    ir[s].x = sd * ir[s].x + c01.x * bs;
                    vr[s].x = md * vr[s].x + ir[s].x;
                    sp.x = sigm(vr[s].x - th);
                    vr[s].x -= sp.x * th;

                    ir[s].y = sd * ir[s].y + c01.y * bs;
                    vr[s].y = md * vr[s].y + ir[s].y;
                    sp.y = sigm(vr[s].y - th);
                    vr[s].y -= sp.y * th;

                    ir[s].z = sd * ir[s].z + c23.x * bs;
                    vr[s].z = md * vr[s].z + ir[s].z;
                    sp.z = sigm(vr[s].z - th);
                    vr[s].z -= sp.z * th;

                    ir[s].w = sd * ir[s].w + c23.y * bs;
                    vr[s].w = md * vr[s].w + ir[s].w;
                    sp.w = sigm(vr[s].w - th);
                    vr[s].w -= sp.w * th;

                    __stcs(o4 + d4, sp);
                }
            }
        }
        // smem reuse safety across steps:
        // - c ping-pong: pass2(t+1) writes slot (t+1)&1, pass3(t) reads slot
        //   t&1 (disjoint); slot reuse at t+2 is by the SAME thread that read
        //   it at t (thread-private mapping) -> program order suffices.
        // - s_rS/s_rW at step k+1 are rewritten only after this warp's s_step
        //   poll for step k passed; their step-k readers (same row-group)
        //   finished before post_asum(k)'s __syncthreads.
        // - s_rA is ping-ponged (same slot rewritten two barriers later).
        // - s_bsv/s_step are monotonic within a launch.
    }
}

extern "C" void kernel_launch(void* const* d_in, const int* in_sizes, int n_in,
                              void* d_out, int out_size)
{
    (void)in_sizes; (void)n_in; (void)out_size;
    const float* x  = (const float*)d_in[0];
    const float* ac = (const float*)d_in[1];
    const float* tw = (const float*)d_in[2];
    const float* ig = (const float*)d_in[3];
    const float* md = (const float*)d_in[4];
    const float* sd = (const float*)d_in[5];
    const float* th = (const float*)d_in[6];
    float* out = (float*)d_out;

    // bytes: c ping-pong 2*NGRP*D4*2 half2 *4B = 64736
    //      + ag DD half2 *4B = 9248
    //      + rS(32)+rW(32)+rA(64)+bsv(1)+step(1) floats = 520
    constexpr size_t SMEM_BYTES =
        (size_t)(2 * NGRP * D4 * 2) * 4 + (size_t)DD * 4 + 130 * 4;  // 74,504 B

    cudaFuncSetAttribute(snn_etad_kernel,
                         cudaFuncAttributeMaxDynamicSharedMemorySize,
                         (int)SMEM_BYTES);

    snn_etad_kernel<<<NBLK, NTHR, SMEM_BYTES>>>(x, ac, tw, ig, md, sd, th, out);
}

// round 10
// speedup vs baseline: 1.0825x; 1.0825x over previous
#include <cuda_runtime.h>
#include <cuda_fp16.h>
#include <cstdint>
#include <cstddef>

// Problem constants
#define TT 20
#define BB 1024
#define DD 2312
#define D4 578            // DD / 4, exact

// Persistent kernel: 147 blocks x 896 threads, 1 block/SM (~74.5KB smem).
// Blocks 0..145 own 7 rows each; block 146 owns rows 1022..1023.
#define NBLK 147
#define NTHR 896
#define GSZ  128          // threads per row-group
#define NGRP 7            // max rows per block
#define NS4  5            // ceil(578/128) float4 slots per thread
#define TAIL4 66          // 578 - 4*128

#define L2E 1.4426950408889634f

// Grid barrier + per-timestep binding-strength accumulators. Restored to
// initial values every launch (20 sense flips -> back to 0; count reset by the
// last arriver; bsum slots cleaned one barrier late) -> graph replays are
// deterministic.
__device__ unsigned g_count = 0;
__device__ unsigned g_sense = 0;
__device__ float    g_bsum[TT];

__device__ __forceinline__ float warp_sum(float v) {
#pragma unroll
    for (int o = 16; o > 0; o >>= 1)
        v += __shfl_xor_sync(0xffffffffu, v, o);
    return v;
}

__device__ __forceinline__ float ex2a(float x) {
    float y; asm("ex2.approx.ftz.f32 %0, %1;" : "=f"(y) : "f"(x)); return y;
}
__device__ __forceinline__ float rcpa(float x) {
    float y; asm("rcp.approx.ftz.f32 %0, %1;" : "=f"(y) : "f"(x)); return y;
}
__device__ __forceinline__ float tanha(float x) {
    float y; asm("tanh.approx.f32 %0, %1;" : "=f"(y) : "f"(x)); return y;
}
// exact-path sigmoid (2 MUFU) — used only in one-time init
__device__ __forceinline__ float sigm(float x) {
    return rcpa(1.0f + ex2a(-x * L2E));
}
// 1-MUFU sigmoid via tanh: sigmoid(x) = 0.5 + 0.5*tanh(x/2).
// tanh.approx.f32 measured (R4->R5 delta) abs err ~1e-5 -> safe even on the
// direct spike-output path (expected output rel err ~1e-4 << 1e-3).
__device__ __forceinline__ float sigm_t(float x) {
    return fmaf(0.5f, tanha(0.5f * x), 0.5f);
}

__device__ __forceinline__ unsigned want_of(int k) { return (unsigned)((k + 1) & 1); }

__global__ void __launch_bounds__(NTHR, 1)
snn_etad_kernel(const float* __restrict__ x,
                const float* __restrict__ ac,
                const float* __restrict__ tw,
                const float* __restrict__ ig,
                const float* __restrict__ p_md,
                const float* __restrict__ p_sd,
                const float* __restrict__ p_th,
                float* __restrict__ out)
{
    extern __shared__ char smraw[];
    // c ping-pong: [2][NGRP][D4*2] half2 (fp16 compressed values)
    __half2* s_c  = (__half2*)smraw;                    // 2*7*1156 half2
    __half2* s_ag = s_c + 2 * NGRP * D4 * 2;            // DD half2 {a, g}
    float*   s_rS = (float*)(s_ag + DD);                // 32
    float*   s_rW = s_rS + 32;                          // 32
    float*   s_rA = s_rW + 32;                          // 2 x 32 ping-pong
    float*   s_bsv = s_rA + 64;                         // 1
    volatile int* s_step = (volatile int*)(s_bsv + 1);  // 1

    const int tid  = threadIdx.x;
    const int grp  = tid >> 7;         // 0..6 row-group
    const int gtid = tid & 127;
    const int w    = tid >> 5;         // 0..27
    const int lane = tid & 31;

    int nrows = BB - NGRP * (int)blockIdx.x;
    nrows = nrows > NGRP ? NGRP : nrows;          // 7 or 2 (block 146)
    const bool rowact = grp < nrows;
    const int b = NGRP * blockIdx.x + grp;        // valid when rowact

    const float md = p_md[0];
    const float sd = p_sd[0];
    const float th = p_th[0];
    const float hth = 0.5f * th;
    const float inv_bd = 1.0f / (float)(BB * DD);

    // Init per-feature gates (fp16 packed {a, g})
    for (int idx = tid; idx < DD; idx += NTHR) {
        const float a = ac[idx];
        const float g = sigm(tw[idx]) * sigm(ig[idx]);
        s_ag[idx] = __floats2half2_rn(a, g);
    }
    if (tid == 0) *s_step = 0;
    __syncthreads();

    // LIF state in registers (thread-private across all steps)
    float4 ir[NS4], vr[NS4];
#pragma unroll
    for (int s = 0; s < NS4; ++s) {
        ir[s] = make_float4(0.f, 0.f, 0.f, 0.f);
        vr[s] = make_float4(0.f, 0.f, 0.f, 0.f);
    }

    // ============ pass1+pass2 for timestep t: writes c(t) fp16 into ping-pong
    // slot (t&1), returns this warp's |c| sum (0 for inactive groups).
    auto compute_c = [&](int t) -> float {
        if (!rowact) return 0.0f;
        const float4* xrow4 = (const float4*)(x + ((size_t)t * BB + b) * DD);
        float4 xv[NS4];
        float S = 0.0f, W = 0.0f;
#pragma unroll
        for (int s = 0; s < NS4; ++s) {
            const int d4 = s * GSZ + gtid;
            const bool act = (s < NS4 - 1) || (gtid < TAIL4);
            if (act) {
                const float4 v = __ldg(xrow4 + d4);
                xv[s] = v;
                float e;
                e = ex2a(v.x * L2E); S += e; W += v.x * e;
                e = ex2a(v.y * L2E); S += e; W += v.y * e;
                e = ex2a(v.z * L2E); S += e; W += v.z * e;
                e = ex2a(v.w * L2E); S += e; W += v.w * e;
            }
        }
        S = warp_sum(S);
        W = warp_sum(W);
        if (lane == 0) { s_rS[w] = S; s_rW[w] = W; }
        asm volatile("bar.sync %0, %1;" :: "r"(grp + 1), "n"(GSZ) : "memory");
        S = s_rS[grp * 4 + 0] + s_rS[grp * 4 + 1] + s_rS[grp * 4 + 2] + s_rS[grp * 4 + 3];
        W = s_rW[grp * 4 + 0] + s_rW[grp * 4 + 1] + s_rW[grp * 4 + 2] + s_rW[grp * 4 + 3];
        // entropy = lnS - W/S - D*1e-8  (shift-invariant; |x|<~6 so no overflow)
        const float ent = __logf(S) - __fdividef(W, S) - (float)DD * 1e-8f;

        __half2* sc2 = s_c + ((unsigned)t & 1) * (NGRP * D4 * 2) + grp * (D4 * 2);
        float asum = 0.0f;
#pragma unroll
        for (int s = 0; s < NS4; ++s) {
            const int d4 = s * GSZ + gtid;
            const bool act = (s < NS4 - 1) || (gtid < TAIL4);
            if (act) {
                const uint4 agp = *(const uint4*)(s_ag + 4 * d4);
                const float2 ag0 = __half22float2(((const __half2*)&agp)[0]);
                const float2 ag1 = __half22float2(((const __half2*)&agp)[1]);
                const float2 ag2 = __half22float2(((const __half2*)&agp)[2]);
                const float2 ag3 = __half22float2(((const __half2*)&agp)[3]);
                float4 c = xv[s];
                c.x = c.x * sigm_t(ag0.x * ent) * ag0.y;
                c.y = c.y * sigm_t(ag1.x * ent) * ag1.y;
                c.z = c.z * sigm_t(ag2.x * ent) * ag2.y;
                c.w = c.w * sigm_t(ag3.x * ent) * ag3.y;
                sc2[d4 * 2 + 0] = __floats2half2_rn(c.x, c.y);
                sc2[d4 * 2 + 1] = __floats2half2_rn(c.z, c.w);
                asum += fabsf(c.x) + fabsf(c.y) + fabsf(c.z) + fabsf(c.w);
            }
        }
        return warp_sum(asum);
    };

    // ============ block-level |c| sum -> s_rA ping-pong + sync + warp0 reduce
    auto post_asum = [&](int k, float asum) -> float {
        if (lane == 0) s_rA[((unsigned)k & 1) * 32 + w] = asum;
        __syncthreads();
        float tot = 0.0f;
        if (w == 0) {
            const float vv = (lane < (NTHR / 32)) ? s_rA[((unsigned)k & 1) * 32 + lane] : 0.0f;
            tot = warp_sum(vv);
        }
        return tot;  // valid in warp 0 only
    };

    // ============ tid0: arrive at global barrier k with this block's total
    auto arrive = [&](int k, float tot) {
        atomicAdd(&g_bsum[k], tot);
        __threadfence();
        const unsigned pos = atomicAdd(&g_count, 1);
        if (pos == NBLK - 1) {
            atomicExch(&g_count, 0u);
            atomicExch(&g_bsum[(k + TT - 1) % TT], 0.0f);   // clean stale slot
            __threadfence();
            atomicExch(&g_sense, want_of(k));
        }
    };

    // ---------------- prologue: c(0) -> slot 0, arrive(0)
    {
        float asum = compute_c(0);
        float tot = post_asum(0, asum);
        if (tid == 0) arrive(0, tot);
    }

    for (int t = 0; t < TT; ++t) {
        // ---- pass1+2 for t+1 (independent of bs(t)) hides barrier latency
        float tot = 0.0f;
        const bool has_next = (t + 1) < TT;
        if (has_next) {
            float asum = compute_c(t + 1);
            tot = post_asum(t + 1, asum);
        } else {
            __syncthreads();
        }

        // ---- tid0: wait barrier t (released ~1 compute-iteration ago),
        //      publish bs(t), then arrive barrier t+1
        if (tid == 0) {
            const unsigned want = want_of(t);
            while (*((volatile unsigned*)&g_sense) != want) __nanosleep(32);
            __threadfence();
            const float bsv = atomicAdd(&g_bsum[t], 0.0f);   // coherent read
            *(volatile float*)s_bsv = bsv * inv_bd;
            __threadfence_block();
            *s_step = t + 1;                                  // publish
            if (has_next) arrive(t + 1, tot);
        }

        // ---- per-warp pickup (warps stagger straight into pass3)
        float bs;
        if (lane == 0) {
            while (*s_step < t + 1) { }
            bs = *(volatile float*)s_bsv;
        }
        bs = __shfl_sync(0xffffffffu, bs, 0);

        // ---- pass3: LIF on c(t) (fp16 ping-pong slot t&1), state in regs.
        // spike = 0.5 + 0.5*tanh((v - th)/2)  (1 MUFU instead of 2)
        if (rowact) {
            const __half2* sc2 = s_c + ((unsigned)t & 1) * (NGRP * D4 * 2) + grp * (D4 * 2);
            float4* o4 = (float4*)(out + ((size_t)t * BB + b) * DD);
#pragma unroll
            for (int s = 0; s < NS4; ++s) {
                const int d4 = s * GSZ + gtid;
                const bool act = (s < NS4 - 1) || (gtid < TAIL4);
                if (act) {
                    const float2 c01 = __half22float2(sc2[d4 * 2 + 0]);
                    const float2 c23 = __half22float2(sc2[d4 * 2 + 1]);
                    float4 sp;

                    ir[s].x = sd * ir[s].x + c01.x * bs;
                    vr[s].x = md * vr[s].x + ir[s].x;
                    sp.x = fmaf(0.5f, tanha(fmaf(0.5f, vr[s].x, -hth)), 0.5f);
                    vr[s].x -= sp.x * th;

                    ir[s].y = sd * ir[s].y + c01.y * bs;
                    vr[s].y = md * vr[s].y + ir[s].y;
                    sp.y = fmaf(0.5f, tanha(fmaf(0.5f, vr[s].y, -hth)), 0.5f);
                    vr[s].y -= sp.y * th;

                    ir[s].z = sd * ir[s].z + c23.x * bs;
                    vr[s].z = md * vr[s].z + ir[s].z;
                    sp.z = fmaf(0.5f, tanha(fmaf(0.5f, vr[s].z, -hth)), 0.5f);
                    vr[s].z -= sp.z * th;

                    ir[s].w = sd * ir[s].w + c23.y * bs;
                    vr[s].w = md * vr[s].w + ir[s].w;
                    sp.w = fmaf(0.5f, tanha(fmaf(0.5f, vr[s].w, -hth)), 0.5f);
                    vr[s].w -= sp.w * th;

                    __stcs(o4 + d4, sp);
                }
            }
        }
        // smem reuse safety across steps:
        // - c ping-pong: pass2(t+1) writes slot (t+1)&1, pass3(t) reads slot
        //   t&1 (disjoint); slot reuse at t+2 is by the SAME thread that read
        //   it at t (thread-private mapping) -> program order suffices.
        // - s_rS/s_rW at step k+1 are rewritten only after this warp's s_step
        //   poll for step k passed; their step-k readers (same row-group)
        //   finished before post_asum(k)'s __syncthreads.
        // - s_rA is ping-ponged (same slot rewritten two barriers later).
        // - s_bsv/s_step are monotonic within a launch.
    }
}

extern "C" void kernel_launch(void* const* d_in, const int* in_sizes, int n_in,
                              void* d_out, int out_size)
{
    (void)in_sizes; (void)n_in; (void)out_size;
    const float* x  = (const float*)d_in[0];
    const float* ac = (const float*)d_in[1];
    const float* tw = (const float*)d_in[2];
    const float* ig = (const float*)d_in[3];
    const float* md = (const float*)d_in[4];
    const float* sd = (const float*)d_in[5];
    const float* th = (const float*)d_in[6];
    float* out = (float*)d_out;

    // bytes: c ping-pong 2*NGRP*D4*2 half2 *4B = 64736
    //      + ag DD half2 *4B = 9248
    //      + rS(32)+rW(32)+rA(64)+bsv(1)+step(1) floats = 520
    constexpr size_t SMEM_BYTES =
        (size_t)(2 * NGRP * D4 * 2) * 4 + (size_t)DD * 4 + 130 * 4;  // 74,504 B

    cudaFuncSetAttribute(snn_etad_kernel,
                         cudaFuncAttributeMaxDynamicSharedMemorySize,
                         (int)SMEM_BYTES);

    snn_etad_kernel<<<NBLK, NTHR, SMEM_BYTES>>>(x, ac, tw, ig, md, sd, th, out);
}